// round 4
// baseline (speedup 1.0000x reference)
#include <cuda_runtime.h>
#include <math.h>

// ---------------- problem constants ----------------
#define NT      256          // threads per block
#define TILE    5120         // envelope outputs per block
#define WIN     240
#define PADW    120
#define CPT     21           // d-elements per thread (NT*CPT=5376 >= TILE+WIN-1=5359)
#define LP      (NT * CPT)   // padded scan length 5376
#define OUT_PT  (TILE / NT)  // 20 outputs per thread
#define EPSF    1e-6f
#define MAXROWS 64
#define MAXBLK  8192

// ---------------- scratch (no allocation allowed) ----------------
__device__ unsigned g_rowmax[MAXROWS];
__device__ double   g_sum1[MAXBLK];   // per-block sum(diff)
__device__ double   g_sum2[MAXBLK];   // per-block sum(diff * Et)

// Register-resident chunk scan:
//   dp[k] = d[j0+k-PADW], d[t] = (1<=t<N) ? |x[t]-x[t-1]| : 0, zero for k>=L.
// Each thread owns the contiguous chunk k in [tid*CPT, tid*CPT+CPT).
// Loads its 22-float x window straight from global (per-warp region is
// contiguous => all fetched lines consumed; overlaps hit L1), scans in
// registers, then a single STS per element writes the final prefix into s[].
__device__ __forceinline__ void build_and_scan(const float* __restrict__ xr,
                                               int j0, int N, int L,
                                               float* __restrict__ s,
                                               float* __restrict__ s_warp)
{
    const int tid  = threadIdx.x;
    const int lane = tid & 31;
    const int wid  = tid >> 5;
    const int c0   = tid * CPT;
    const int t0   = j0 + c0 - PADW;     // d-index of first chunk element

    float pref[CPT];
    int tm1 = t0 - 1;
    float xprev = (tm1 >= 0 && tm1 < N) ? xr[tm1] : 0.f;
    float run = 0.f;
#pragma unroll
    for (int i = 0; i < CPT; i++) {
        int t = t0 + i;
        float xi = ((unsigned)t < (unsigned)N) ? xr[t] : 0.f;
        float d  = (t >= 1 && t < N && (c0 + i) < L) ? fabsf(xi - xprev) : 0.f;
        run += d;
        pref[i] = run;
        xprev = xi;
    }

    // shuffle scan over the 256 chunk totals
    float tot = run;
#pragma unroll
    for (int off = 1; off < 32; off <<= 1) {
        float v = __shfl_up_sync(0xFFFFFFFFu, tot, off);
        if (lane >= off) tot += v;
    }
    if (lane == 31) s_warp[wid] = tot;
    __syncthreads();
    if (wid == 0) {
        float w = (lane < (NT / 32)) ? s_warp[lane] : 0.f;
#pragma unroll
        for (int off = 1; off < (NT / 32); off <<= 1) {
            float v = __shfl_up_sync(0xFFFFFFFFu, w, off);
            if (lane >= off) w += v;
        }
        if (lane < (NT / 32)) s_warp[lane] = w;
    }
    __syncthreads();

    const float add = ((wid > 0) ? s_warp[wid - 1] : 0.f) + (tot - run);
    // single STS per element; stride 21 coprime with 32 banks -> conflict-free
#pragma unroll
    for (int i = 0; i < CPT; i++) s[c0 + i] = pref[i] + add;
    __syncthreads();
}

__global__ void zeroKernel()
{
    if (threadIdx.x < MAXROWS) g_rowmax[threadIdx.x] = 0u;
}

// Fused: per tile computes Ep, Et; accumulates S1 = sum(diff), S2 = sum(diff*Et),
// and the row max of Et. Row-max weighting is applied in finalKernel:
//   loss_row = 0.2*S1 + 0.8*S2/(rowmax+eps)
__global__ __launch_bounds__(NT) void fusedKernel(const float* __restrict__ yp,
                                                  const float* __restrict__ yt,
                                                  int N, int nOut)
{
    __shared__ float  s_t[LP];
    __shared__ float  s_p[LP];
    __shared__ float  s_warp[NT / 32];
    __shared__ double r1[NT / 32], r2[NT / 32];
    __shared__ float  rm[NT / 32];

    const int row = blockIdx.y;
    const int j0  = blockIdx.x * TILE;
    const int L   = TILE + WIN - 1;
    build_and_scan(yt + (size_t)row * N, j0, N, L, s_t, s_warp);
    build_and_scan(yp + (size_t)row * N, j0, N, L, s_p, s_warp);

    const float invW = 1.0f / (float)WIN;
    const int tid  = threadIdx.x;
    const int lane = tid & 31;
    const int wid  = tid >> 5;

    float f1 = 0.f, f2 = 0.f, m = 0.f;   // per-thread float accumulators (20 adds)
#pragma unroll
    for (int oi = 0; oi < OUT_PT; oi++) {
        int i = tid + oi * NT;             // strided -> conflict-free shared reads
        int j = j0 + i;
        if (j < nOut) {
            float pt = (i > 0) ? s_t[i - 1] : 0.f;
            float pp = (i > 0) ? s_p[i - 1] : 0.f;
            float Et = (s_t[i + WIN - 1] - pt) * invW;
            float Ep = (s_p[i + WIN - 1] - pp) * invW;
            // fast log: 2x MUFU.LG2 instead of the precise logf software sequence
            float diff = fabsf(__logf(Ep + EPSF) - __logf(Et + EPSF));
            f1 += diff;
            f2 += diff * Et;
            m = fmaxf(m, Et);
        }
    }
    double a1 = (double)f1, a2 = (double)f2;
    // warp reductions (double for the sums to keep 7.7M-element total exact enough)
#pragma unroll
    for (int off = 16; off > 0; off >>= 1) {
        a1 += __shfl_down_sync(0xFFFFFFFFu, a1, off);
        a2 += __shfl_down_sync(0xFFFFFFFFu, a2, off);
        m   = fmaxf(m, __shfl_down_sync(0xFFFFFFFFu, m, off));
    }
    if (lane == 0) { r1[wid] = a1; r2[wid] = a2; rm[wid] = m; }
    __syncthreads();
    if (wid == 0 && lane < (NT / 32)) {
        a1 = r1[lane]; a2 = r2[lane]; m = rm[lane];
#pragma unroll
        for (int off = (NT / 64); off > 0; off >>= 1) {
            a1 += __shfl_down_sync(0xFFFFFFFFu, a1, off);
            a2 += __shfl_down_sync(0xFFFFFFFFu, a2, off);
            m   = fmaxf(m, __shfl_down_sync(0xFFFFFFFFu, m, off));
        }
        if (lane == 0) {
            size_t b = (size_t)row * gridDim.x + blockIdx.x;
            g_sum1[b] = a1;
            g_sum2[b] = a2;
            atomicMax(&g_rowmax[row], __float_as_uint(m));
        }
    }
}

// One block: warp r reduces row r's tiles, combines with rowmax, then sums rows.
__global__ __launch_bounds__(512) void finalKernel(float* __restrict__ out,
                                                   int tiles, int B, double invCount)
{
    __shared__ double srow[16];
    const int lane = threadIdx.x & 31;
    const int w    = threadIdx.x >> 5;

    if (w < B) {
        double s1 = 0.0, s2 = 0.0;
        for (int t = lane; t < tiles; t += 32) {
            size_t b = (size_t)w * tiles + t;
            s1 += g_sum1[b];
            s2 += g_sum2[b];
        }
#pragma unroll
        for (int off = 16; off > 0; off >>= 1) {
            s1 += __shfl_down_sync(0xFFFFFFFFu, s1, off);
            s2 += __shfl_down_sync(0xFFFFFFFFu, s2, off);
        }
        if (lane == 0) {
            float rmax = __uint_as_float(g_rowmax[w]);
            srow[w] = 0.2 * s1 + 0.8 * s2 / ((double)rmax + (double)EPSF);
        }
    }
    __syncthreads();
    if (threadIdx.x == 0) {
        double tot = 0.0;
        for (int r = 0; r < B; r++) tot += srow[r];
        out[0] = (float)(tot * invCount);
    }
}

extern "C" void kernel_launch(void* const* d_in, const int* in_sizes, int n_in,
                              void* d_out, int out_size)
{
    const float* yp = (const float*)d_in[0];
    const float* yt = (const float*)d_in[1];

    const int B = 16;
    const int N = in_sizes[0] / B;       // 480000
    const int nOut = N + 1;              // 480001
    const int tiles = (nOut + TILE - 1) / TILE;   // 94
    dim3 grid(tiles, B);

    zeroKernel<<<1, MAXROWS>>>();
    fusedKernel<<<grid, NT>>>(yp, yt, N, nOut);

    const double invCount = 1.0 / ((double)B * (double)nOut);
    finalKernel<<<1, 512>>>((float*)d_out, tiles, B, invCount);
}

// round 5
// speedup vs baseline: 1.2383x; 1.2383x over previous
#include <cuda_runtime.h>
#include <math.h>

// ---------------- problem constants ----------------
#define NT      256          // threads per block
#define TILE    5120         // envelope outputs per block
#define WIN     240
#define PADW    120
#define CPT     21           // d-elements per thread (NT*CPT=5376 >= TILE+WIN-1=5359)
#define LP      (NT * CPT)   // padded scan length 5376
#define OUT_PT  (TILE / NT)  // 20 outputs per thread
#define EPSF    1e-6f
#define MAXBLK  8192

// ---------------- scratch (no allocation allowed) ----------------
__device__ double g_s1[MAXBLK];   // per-block sum(diff)
__device__ double g_s2[MAXBLK];   // per-block sum(diff * Et)
__device__ float  g_mx[MAXBLK];   // per-block max(Et)   (no atomics, no zeroing)

// Stage raw x into smem coalesced, then register-scan per-thread chunks and
// write the inclusive prefix of dp back into the SAME buffer (in place).
//   stage[k] = x[j0-PADW-1+k]  (0 outside [0,N)),  k in [0, LP]
//   dp[k]    = d[j0+k-PADW],  d[t] = (1<=t<N) ? |x[t]-x[t-1]| : 0,  0 for k>=L
// After return, s[k] = inclusive prefix sum of dp[0..k].
__device__ __forceinline__ void build_and_scan(const float* __restrict__ xr,
                                               int j0, int N, int L,
                                               float* __restrict__ s,
                                               float* __restrict__ s_warp)
{
    const int tid  = threadIdx.x;
    const int lane = tid & 31;
    const int wid  = tid >> 5;
    const int c0   = tid * CPT;

    // coalesced stage: consecutive lanes -> consecutive addresses (1 line / warp LDG)
    const int base = j0 - PADW - 1;
    for (int k = tid; k <= LP; k += NT) {
        int t = base + k;
        s[k] = ((unsigned)t < (unsigned)N) ? xr[t] : 0.f;
    }
    __syncthreads();

    // per-thread chunk: read 22 staged values (stride-21 chunks -> conflict-free),
    // form diffs + running prefix in registers
    float xv[CPT + 1];
#pragma unroll
    for (int i = 0; i <= CPT; i++) xv[i] = s[c0 + i];

    float pref[CPT];
    float run = 0.f;
#pragma unroll
    for (int i = 0; i < CPT; i++) {
        int k = c0 + i;
        int t = j0 + k - PADW;
        float d = (t >= 1 && t < N && k < L) ? fabsf(xv[i + 1] - xv[i]) : 0.f;
        run += d;
        pref[i] = run;
    }

    // shuffle scan over the 256 chunk totals
    float tot = run;
#pragma unroll
    for (int off = 1; off < 32; off <<= 1) {
        float v = __shfl_up_sync(0xFFFFFFFFu, tot, off);
        if (lane >= off) tot += v;
    }
    if (lane == 31) s_warp[wid] = tot;
    __syncthreads();                       // also guards: all stage reads done
    if (wid == 0) {
        float w = (lane < (NT / 32)) ? s_warp[lane] : 0.f;
#pragma unroll
        for (int off = 1; off < (NT / 32); off <<= 1) {
            float v = __shfl_up_sync(0xFFFFFFFFu, w, off);
            if (lane >= off) w += v;
        }
        if (lane < (NT / 32)) s_warp[lane] = w;
    }
    __syncthreads();

    const float add = ((wid > 0) ? s_warp[wid - 1] : 0.f) + (tot - run);
    // in-place: overwrite stage with final prefix (single STS per element)
#pragma unroll
    for (int i = 0; i < CPT; i++) s[c0 + i] = pref[i] + add;
    __syncthreads();
}

// Fused: per tile computes Ep, Et; writes per-block S1 = sum(diff),
// S2 = sum(diff*Et), M = max(Et). Weighting happens in finalKernel:
//   loss_row = 0.2*S1 + 0.8*S2/(rowmax+eps)
__global__ __launch_bounds__(NT) void fusedKernel(const float* __restrict__ yp,
                                                  const float* __restrict__ yt,
                                                  int N, int nOut)
{
    __shared__ float  s_t[LP + 1];
    __shared__ float  s_p[LP + 1];
    __shared__ float  s_warp[NT / 32];
    __shared__ double r1[NT / 32], r2[NT / 32];
    __shared__ float  rm[NT / 32];

    const int row = blockIdx.y;
    const int j0  = blockIdx.x * TILE;
    const int L   = TILE + WIN - 1;
    build_and_scan(yt + (size_t)row * N, j0, N, L, s_t, s_warp);
    build_and_scan(yp + (size_t)row * N, j0, N, L, s_p, s_warp);

    const float invW = 1.0f / (float)WIN;
    const int tid  = threadIdx.x;
    const int lane = tid & 31;
    const int wid  = tid >> 5;

    float f1 = 0.f, f2 = 0.f, m = 0.f;   // per-thread float accumulators (20 adds)
#pragma unroll
    for (int oi = 0; oi < OUT_PT; oi++) {
        int i = tid + oi * NT;             // strided -> conflict-free shared reads
        int j = j0 + i;
        if (j < nOut) {
            float pt = (i > 0) ? s_t[i - 1] : 0.f;
            float pp = (i > 0) ? s_p[i - 1] : 0.f;
            float Et = (s_t[i + WIN - 1] - pt) * invW;
            float Ep = (s_p[i + WIN - 1] - pp) * invW;
            // fast log: 2x MUFU.LG2 instead of the precise logf software sequence
            float diff = fabsf(__logf(Ep + EPSF) - __logf(Et + EPSF));
            f1 += diff;
            f2 += diff * Et;
            m = fmaxf(m, Et);
        }
    }
    double a1 = (double)f1, a2 = (double)f2;
#pragma unroll
    for (int off = 16; off > 0; off >>= 1) {
        a1 += __shfl_down_sync(0xFFFFFFFFu, a1, off);
        a2 += __shfl_down_sync(0xFFFFFFFFu, a2, off);
        m   = fmaxf(m, __shfl_down_sync(0xFFFFFFFFu, m, off));
    }
    if (lane == 0) { r1[wid] = a1; r2[wid] = a2; rm[wid] = m; }
    __syncthreads();
    if (wid == 0 && lane < (NT / 32)) {
        a1 = r1[lane]; a2 = r2[lane]; m = rm[lane];
#pragma unroll
        for (int off = (NT / 64); off > 0; off >>= 1) {
            a1 += __shfl_down_sync(0xFFFFFFFFu, a1, off);
            a2 += __shfl_down_sync(0xFFFFFFFFu, a2, off);
            m   = fmaxf(m, __shfl_down_sync(0xFFFFFFFFu, m, off));
        }
        if (lane == 0) {
            size_t b = (size_t)row * gridDim.x + blockIdx.x;
            g_s1[b] = a1;
            g_s2[b] = a2;
            g_mx[b] = m;                 // plain store: no atomic, no pre-zero
        }
    }
}

// One block, warp r owns row r: reduce tile sums + max, weight, sum rows.
__global__ __launch_bounds__(512) void finalKernel(float* __restrict__ out,
                                                   int tiles, int B, double invCount)
{
    __shared__ double srow[16];
    const int lane = threadIdx.x & 31;
    const int w    = threadIdx.x >> 5;

    if (w < B) {
        double s1 = 0.0, s2 = 0.0;
        float  m  = 0.f;
        for (int t = lane; t < tiles; t += 32) {
            size_t b = (size_t)w * tiles + t;
            s1 += g_s1[b];
            s2 += g_s2[b];
            m   = fmaxf(m, g_mx[b]);
        }
#pragma unroll
        for (int off = 16; off > 0; off >>= 1) {
            s1 += __shfl_down_sync(0xFFFFFFFFu, s1, off);
            s2 += __shfl_down_sync(0xFFFFFFFFu, s2, off);
            m   = fmaxf(m, __shfl_down_sync(0xFFFFFFFFu, m, off));
        }
        if (lane == 0)
            srow[w] = 0.2 * s1 + 0.8 * s2 / ((double)m + (double)EPSF);
    }
    __syncthreads();
    if (threadIdx.x == 0) {
        double tot = 0.0;
        for (int r = 0; r < B; r++) tot += srow[r];
        out[0] = (float)(tot * invCount);
    }
}

extern "C" void kernel_launch(void* const* d_in, const int* in_sizes, int n_in,
                              void* d_out, int out_size)
{
    const float* yp = (const float*)d_in[0];
    const float* yt = (const float*)d_in[1];

    const int B = 16;
    const int N = in_sizes[0] / B;       // 480000
    const int nOut = N + 1;              // 480001
    const int tiles = (nOut + TILE - 1) / TILE;   // 94
    dim3 grid(tiles, B);

    fusedKernel<<<grid, NT>>>(yp, yt, N, nOut);

    const double invCount = 1.0 / ((double)B * (double)nOut);
    finalKernel<<<1, 512>>>((float*)d_out, tiles, B, invCount);
}